// round 7
// baseline (speedup 1.0000x reference)
#include <cuda_runtime.h>
#include <cstdint>

// GridCellRouter: H=W=4096, N=16,777,216 cells, 16 iterations.
//   accum = scatter_add(accum, flow_idx, cur)
//   cur   = accum - cur
//
// Round 3: revert L2 eviction-policy experiment (hurt steady-state replay);
// keep cur default-cached so it hands off through L2 between phases;
// repack 32-bit indices (< 2^24) into u16 lo + u8 hi once per call,
// cutting the per-iteration index stream from 64 MB to 48 MB.

#define N_CELLS (4096 * 4096)
#define ITERS 16

__device__ float   g_cur[N_CELLS];      // 64 MB scratch
__device__ ushort4 g_idx_lo[N_CELLS/4]; // 32 MB: low 16 bits of idx
__device__ uchar4  g_idx_hi[N_CELLS/4]; // 16 MB: bits 16..23 of idx

// One-time per call: split 32-bit indices into 16+8 bit planes.
__global__ void pack_kernel(const int4* __restrict__ idx,
                            ushort4* __restrict__ lo,
                            uchar4* __restrict__ hi, int n4) {
    int t = blockIdx.x * blockDim.x + threadIdx.x;
    if (t >= n4) return;
    int4 v = __ldcs(idx + t);
    lo[t] = make_ushort4((unsigned short)(v.x & 0xFFFF),
                         (unsigned short)(v.y & 0xFFFF),
                         (unsigned short)(v.z & 0xFFFF),
                         (unsigned short)(v.w & 0xFFFF));
    hi[t] = make_uchar4((unsigned char)(v.x >> 16),
                        (unsigned char)(v.y >> 16),
                        (unsigned char)(v.z >> 16),
                        (unsigned char)(v.w >> 16));
}

// accum = runoff (d_out is poisoned; must be initialized).
__global__ void init_kernel(const float4* __restrict__ runoff,
                            float4* __restrict__ accum, int n4) {
    int i = blockIdx.x * blockDim.x + threadIdx.x;
    if (i < n4) accum[i] = runoff[i];
}

// Phase 1: atomicAdd(accum[idx[i]], cur[i]).  idx streams evict-first,
// cur default (expected L2-hot from previous update).
__global__ void scatter_kernel(const float* __restrict__ cur,
                               const ushort4* __restrict__ lo,
                               const uchar4* __restrict__ hi,
                               float* __restrict__ accum, int n4) {
    int t = blockIdx.x * blockDim.x + threadIdx.x;
    if (t >= n4) return;
    float4 c = reinterpret_cast<const float4*>(cur)[t];
    ushort4 l = __ldcs(lo + t);
    uchar4  h = __ldcs(hi + t);
    int dx = (int)l.x | ((int)h.x << 16);
    int dy = (int)l.y | ((int)h.y << 16);
    int dz = (int)l.z | ((int)h.z << 16);
    int dw = (int)l.w | ((int)h.w << 16);
    atomicAdd(accum + dx, c.x);   // result unused -> RED.E.ADD.F32
    atomicAdd(accum + dy, c.y);
    atomicAdd(accum + dz, c.z);
    atomicAdd(accum + dw, c.w);
}

// Phase 2: cur_out[i] = accum[i] - cur_in[i].  All default policy:
// accum hot from atomics, cur_in hot from scatter read, cur_out stays
// resident for the next scatter.
__global__ void update_kernel(const float4* __restrict__ accum,
                              const float* __restrict__ cur_in,
                              float* __restrict__ cur_out, int n4) {
    int t = blockIdx.x * blockDim.x + threadIdx.x;
    if (t >= n4) return;
    float4 a = accum[t];
    float4 c = reinterpret_cast<const float4*>(cur_in)[t];
    float4 o;
    o.x = a.x - c.x; o.y = a.y - c.y; o.z = a.z - c.z; o.w = a.w - c.w;
    reinterpret_cast<float4*>(cur_out)[t] = o;
}

extern "C" void kernel_launch(void* const* d_in, const int* in_sizes, int n_in,
                              void* d_out, int out_size) {
    const float* runoff = (const float*)d_in[0];
    const int* flow_idx = (const int*)d_in[1];
    float* accum = (float*)d_out;

    float* cur = nullptr;
    ushort4* lo = nullptr;
    uchar4* hi = nullptr;
    cudaGetSymbolAddress((void**)&cur, g_cur);
    cudaGetSymbolAddress((void**)&lo, g_idx_lo);
    cudaGetSymbolAddress((void**)&hi, g_idx_hi);

    const int n4 = N_CELLS / 4;                       // 4,194,304
    const int threads = 256;
    const int blocks = (n4 + threads - 1) / threads;  // 16,384

    pack_kernel<<<blocks, threads>>>((const int4*)flow_idx, lo, hi, n4);
    init_kernel<<<blocks, threads>>>((const float4*)runoff, (float4*)accum, n4);

    const float* cur_src = runoff;                    // iteration 1 reads runoff directly
    for (int it = 0; it < ITERS; ++it) {
        scatter_kernel<<<blocks, threads>>>(cur_src, lo, hi, accum, n4);
        update_kernel<<<blocks, threads>>>((const float4*)accum, cur_src, cur, n4);
        cur_src = cur;
    }
}

// round 8
// speedup vs baseline: 1.1711x; 1.1711x over previous
#include <cuda_runtime.h>

// GridCellRouter: H=W=4096, N=16,777,216 cells, 16 iterations.
// Reference:  A_t = A_{t-1} + S*c_{t-1};  c_t = A_t - c_{t-1}
// Identity:   A_t - c_t = c_{t-1}   =>   c_t = S*c_{t-1} + c_{t-2}
//             with c_0 = runoff, c_{-1} = 0, and  A_16 = c_16 + c_15.
//
// So each iteration is ONE scatter-add of c_{t-1} into the buffer that
// already holds c_{t-2} (ping-pong, in place). The update pass (3x64MB
// streams/iter) is eliminated entirely. Streams are .cs so L2 stays
// dedicated to the atomic target (lesson from rounds 2/3: cur-as-default
// evicts the target and regresses).

#define N_CELLS (4096 * 4096)
#define ITERS 16

__device__ float g_x[N_CELLS];   // 64 MB ping
__device__ float g_y[N_CELLS];   // 64 MB pong

__device__ __forceinline__ float4 ldcs_f4(const float4* p) {
    float4 v;
    asm volatile("ld.global.cs.v4.f32 {%0,%1,%2,%3}, [%4];"
                 : "=f"(v.x), "=f"(v.y), "=f"(v.z), "=f"(v.w) : "l"(p));
    return v;
}
__device__ __forceinline__ int4 ldcs_i4(const int4* p) {
    int4 v;
    asm volatile("ld.global.cs.v4.b32 {%0,%1,%2,%3}, [%4];"
                 : "=r"(v.x), "=r"(v.y), "=r"(v.z), "=r"(v.w) : "l"(p));
    return v;
}

// X = runoff (= c_0), Y = 0 (= c_{-1})
__global__ void init_kernel(const float4* __restrict__ runoff,
                            float4* __restrict__ x,
                            float4* __restrict__ y, int n4) {
    int i = blockIdx.x * blockDim.x + threadIdx.x;
    if (i >= n4) return;
    x[i] = ldcs_f4(runoff + i);
    y[i] = make_float4(0.f, 0.f, 0.f, 0.f);
}

// dst += S * src   (dst already holds c_{t-2}; becomes c_t)
__global__ void scatter_kernel(const float* __restrict__ src,
                               const int* __restrict__ idx,
                               float* __restrict__ dst, int n4) {
    int t = blockIdx.x * blockDim.x + threadIdx.x;
    if (t >= n4) return;
    float4 c = ldcs_f4(reinterpret_cast<const float4*>(src) + t);
    int4 d = ldcs_i4(reinterpret_cast<const int4*>(idx) + t);
    atomicAdd(dst + d.x, c.x);   // result unused -> RED.E.ADD.F32
    atomicAdd(dst + d.y, c.y);
    atomicAdd(dst + d.z, c.z);
    atomicAdd(dst + d.w, c.w);
}

// out = c_16 + c_15
__global__ void final_kernel(const float4* __restrict__ x,
                             const float4* __restrict__ y,
                             float4* __restrict__ out, int n4) {
    int t = blockIdx.x * blockDim.x + threadIdx.x;
    if (t >= n4) return;
    float4 a = ldcs_f4(x + t);
    float4 b = ldcs_f4(y + t);
    float4 o;
    o.x = a.x + b.x; o.y = a.y + b.y; o.z = a.z + b.z; o.w = a.w + b.w;
    out[t] = o;
}

extern "C" void kernel_launch(void* const* d_in, const int* in_sizes, int n_in,
                              void* d_out, int out_size) {
    const float* runoff = (const float*)d_in[0];
    const int* flow_idx = (const int*)d_in[1];
    float* out = (float*)d_out;

    float* X = nullptr;
    float* Y = nullptr;
    cudaGetSymbolAddress((void**)&X, g_x);
    cudaGetSymbolAddress((void**)&Y, g_y);

    const int n4 = N_CELLS / 4;                       // 4,194,304
    const int threads = 256;
    const int blocks = (n4 + threads - 1) / threads;  // 16,384

    // X = c_0 = runoff, Y = c_{-1} = 0
    init_kernel<<<blocks, threads>>>((const float4*)runoff, (float4*)X, (float4*)Y, n4);

    // c_t = S*c_{t-1} + c_{t-2}, scattering into the c_{t-2} buffer in place.
    // it even: src = X (c_{t-1}), dst = Y;  it odd: src = Y, dst = X.
    for (int it = 0; it < ITERS; ++it) {
        if ((it & 1) == 0)
            scatter_kernel<<<blocks, threads>>>(X, flow_idx, Y, n4);
        else
            scatter_kernel<<<blocks, threads>>>(Y, flow_idx, X, n4);
    }
    // After 16 iters (last was it=15, odd): X = c_16, Y = c_15.
    final_kernel<<<blocks, threads>>>((const float4*)X, (const float4*)Y, (float4*)out, n4);
}